// round 11
// baseline (speedup 1.0000x reference)
#include <cuda_runtime.h>
#include <math.h>
#include <stdint.h>

#define B_SZ 16384
#define D_SZ 4096
#define H_SZ 128
#define E_SZ 64
#define K_TOP 8

__device__ __forceinline__ uint32_t f2tf32(float x) {
    uint32_t r;
    asm("cvt.rna.tf32.f32 %0, %1;" : "=r"(r) : "f"(x));
    return r;
}
__device__ __forceinline__ void split_tf32(float x, uint32_t& hi, uint32_t& lo) {
    hi = f2tf32(x);
    lo = f2tf32(x - __uint_as_float(hi));
}

#define MMA_TF32(C, A0, A1, A2, A3, B0, B1)                                   \
    asm volatile(                                                             \
        "mma.sync.aligned.m16n8k8.row.col.f32.tf32.tf32.f32 "                 \
        "{%0,%1,%2,%3}, {%4,%5,%6,%7}, {%8,%9}, {%0,%1,%2,%3};"               \
        : "+f"(C[0]), "+f"(C[1]), "+f"(C[2]), "+f"(C[3])                      \
        : "r"(A0), "r"(A1), "r"(A2), "r"(A3), "r"(B0), "r"(B1))

// ---------------------------------------------------------------------------
// Fused kernel: h = silu(features @ W1 + b1) [3xTF32 mma.sync, 2-stage pipe]
// then logits = h @ W2 + b2, top-8, softmax, scatter [in-block epilogue].
// BM=64, BN=128(H), BK=32. 256 threads = 8 warps (2m x 4n), warp tile 32x32.
// 2 CTAs / SM: independent barriers + pipelines overlap; grid 256 lights all
// 148 SMs (vs 128 with BM=128).
// ---------------------------------------------------------------------------
#define BM 64
#define BK 32
#define AS_STRIDE 36   // bank(4r + 8ks + tg): frag loads conflict-free
#define BS_STRIDE 136  // bank(8tg + g): frag loads conflict-free

#define A_STG   (BM * AS_STRIDE)         // 2304 u32
#define B_STG   (BK * BS_STRIDE)         // 4352 u32
#define STG     (2 * A_STG + 2 * B_STG)  // 13312 u32 per stage
#define OFF_AH(s) ((s) * STG + 0)
#define OFF_AL(s) ((s) * STG + A_STG)
#define OFF_BH(s) ((s) * STG + 2 * A_STG)
#define OFF_BL(s) ((s) * STG + 2 * A_STG + B_STG)
#define SMEM_U32  (2 * STG)              // 26624 u32 = 106496 bytes

// epilogue overlays: hs (64 x HS_STRIDE f32) on stage 0, ws2 pairs on stage 1
#define HS_STRIDE 132                    // 64*132 = 8448 u32 <= STG

__global__ __launch_bounds__(256, 2)
void fused_router_kernel(const float* __restrict__ A,     // (B, D)
                         const float* __restrict__ W1,    // (D+3, H)
                         const float* __restrict__ b1,    // (H)
                         const float* __restrict__ stepp, // (1)
                         const float* __restrict__ hn,    // (B)
                         const float* __restrict__ conf,  // (B)
                         const float* __restrict__ W2,    // (H, E)
                         const float* __restrict__ b2,    // (E)
                         float* __restrict__ out)
{
    extern __shared__ uint32_t smem[];

    const int tid  = threadIdx.x;
    const int lane = tid & 31;
    const int w    = tid >> 5;       // 0..7
    const int wm   = (w & 1) * 32;   // 2 warps in m
    const int wn   = (w >> 1) * 32;  // 4 warps in n
    const int g    = lane >> 2;
    const int tg   = lane & 3;
    const int m0   = blockIdx.x * BM;

    float acc[2][4][4];
    float sum[2][4][4];
#pragma unroll
    for (int mi = 0; mi < 2; ++mi)
#pragma unroll
        for (int ni = 0; ni < 4; ++ni)
#pragma unroll
            for (int c = 0; c < 4; ++c) { acc[mi][ni][c] = 0.0f; sum[mi][ni][c] = 0.0f; }

    // Writer mapping per iteration:
    // A tile 64x32 = 512 float4 (2/thread): f = i*256+tid, row=f>>3, c4=f&7
    // B tile 32x128 = 1024 float4 (4/thread): f = i*256+tid, row=f>>5, c4=f&31
    float4 pa[2], pb[4];
#pragma unroll
    for (int i = 0; i < 2; ++i) {
        int f = i * 256 + tid;
        pa[i] = *(const float4*)&A[(size_t)(m0 + (f >> 3)) * D_SZ + (f & 7) * 4];
    }
#pragma unroll
    for (int i = 0; i < 4; ++i) {
        int f = i * 256 + tid;
        pb[i] = *(const float4*)&W1[(size_t)(f >> 5) * H_SZ + (f & 31) * 4];
    }

    // prologue: fill stage 0
#pragma unroll
    for (int i = 0; i < 2; ++i) {
        int f = i * 256 + tid;
        uint4 h4, l4;
        split_tf32(pa[i].x, h4.x, l4.x); split_tf32(pa[i].y, h4.y, l4.y);
        split_tf32(pa[i].z, h4.z, l4.z); split_tf32(pa[i].w, h4.w, l4.w);
        int ao = (f >> 3) * AS_STRIDE + (f & 7) * 4;
        *(uint4*)&smem[OFF_AH(0) + ao] = h4;
        *(uint4*)&smem[OFF_AL(0) + ao] = l4;
    }
#pragma unroll
    for (int i = 0; i < 4; ++i) {
        int f = i * 256 + tid;
        uint4 h4, l4;
        split_tf32(pb[i].x, h4.x, l4.x); split_tf32(pb[i].y, h4.y, l4.y);
        split_tf32(pb[i].z, h4.z, l4.z); split_tf32(pb[i].w, h4.w, l4.w);
        int bo = (f >> 5) * BS_STRIDE + (f & 31) * 4;
        *(uint4*)&smem[OFF_BH(0) + bo] = h4;
        *(uint4*)&smem[OFF_BL(0) + bo] = l4;
    }

    const int NIT = D_SZ / BK;   // 128
    for (int it = 0; it < NIT; ++it) {
        __syncthreads();
        const int cur = it & 1;
        const bool pre = (it + 1 < NIT);

        if (pre) {
            int k0 = (it + 1) * BK;
#pragma unroll
            for (int i = 0; i < 2; ++i) {
                int f = i * 256 + tid;
                pa[i] = *(const float4*)&A[(size_t)(m0 + (f >> 3)) * D_SZ + k0 + (f & 7) * 4];
            }
#pragma unroll
            for (int i = 0; i < 4; ++i) {
                int f = i * 256 + tid;
                pb[i] = *(const float4*)&W1[(size_t)(k0 + (f >> 5)) * H_SZ + (f & 31) * 4];
            }
        }

        const uint32_t* AsH = &smem[OFF_AH(cur)];
        const uint32_t* AsL = &smem[OFF_AL(cur)];
        const uint32_t* BsH = &smem[OFF_BH(cur)];
        const uint32_t* BsL = &smem[OFF_BL(cur)];

#pragma unroll
        for (int ks = 0; ks < 4; ++ks) {
            uint32_t aH[2][4], aL[2][4], bH[4][2], bL[4][2];
#pragma unroll
            for (int mi = 0; mi < 2; ++mi) {
                int base = (wm + mi * 16 + g) * AS_STRIDE + ks * 8 + tg;
                aH[mi][0] = AsH[base];
                aH[mi][1] = AsH[base + 8 * AS_STRIDE];
                aH[mi][2] = AsH[base + 4];
                aH[mi][3] = AsH[base + 8 * AS_STRIDE + 4];
                aL[mi][0] = AsL[base];
                aL[mi][1] = AsL[base + 8 * AS_STRIDE];
                aL[mi][2] = AsL[base + 4];
                aL[mi][3] = AsL[base + 8 * AS_STRIDE + 4];
            }
#pragma unroll
            for (int ni = 0; ni < 4; ++ni) {
                int base = (ks * 8 + tg) * BS_STRIDE + wn + ni * 8 + g;
                bH[ni][0] = BsH[base];
                bH[ni][1] = BsH[base + 4 * BS_STRIDE];
                bL[ni][0] = BsL[base];
                bL[ni][1] = BsL[base + 4 * BS_STRIDE];
            }
#pragma unroll
            for (int mi = 0; mi < 2; ++mi)
#pragma unroll
                for (int ni = 0; ni < 4; ++ni) {
                    float* c = acc[mi][ni];
                    MMA_TF32(c, aL[mi][0], aL[mi][1], aL[mi][2], aL[mi][3],
                             bH[ni][0], bH[ni][1]);
                    MMA_TF32(c, aH[mi][0], aH[mi][1], aH[mi][2], aH[mi][3],
                             bL[ni][0], bL[ni][1]);
                    MMA_TF32(c, aH[mi][0], aH[mi][1], aH[mi][2], aH[mi][3],
                             bH[ni][0], bH[ni][1]);
                }
        }

        if (pre) {
            const int nxt = cur ^ 1;
#pragma unroll
            for (int i = 0; i < 2; ++i) {
                int f = i * 256 + tid;
                uint4 h4, l4;
                split_tf32(pa[i].x, h4.x, l4.x); split_tf32(pa[i].y, h4.y, l4.y);
                split_tf32(pa[i].z, h4.z, l4.z); split_tf32(pa[i].w, h4.w, l4.w);
                int ao = (f >> 3) * AS_STRIDE + (f & 7) * 4;
                *(uint4*)&smem[OFF_AH(nxt) + ao] = h4;
                *(uint4*)&smem[OFF_AL(nxt) + ao] = l4;
            }
#pragma unroll
            for (int i = 0; i < 4; ++i) {
                int f = i * 256 + tid;
                uint4 h4, l4;
                split_tf32(pb[i].x, h4.x, l4.x); split_tf32(pb[i].y, h4.y, l4.y);
                split_tf32(pb[i].z, h4.z, l4.z); split_tf32(pb[i].w, h4.w, l4.w);
                int bo = (f >> 5) * BS_STRIDE + (f & 31) * 4;
                *(uint4*)&smem[OFF_BH(nxt) + bo] = h4;
                *(uint4*)&smem[OFF_BL(nxt) + bo] = l4;
            }
        }

        // drain RZ accumulators into RN sums every 2 iters (64 k), validated
        if ((it & 1) == 1) {
#pragma unroll
            for (int mi = 0; mi < 2; ++mi)
#pragma unroll
                for (int ni = 0; ni < 4; ++ni)
#pragma unroll
                    for (int c = 0; c < 4; ++c) {
                        sum[mi][ni][c] += acc[mi][ni][c];
                        acc[mi][ni][c] = 0.0f;
                    }
        }
    }

    // ---- epilogue stage A: rank-1 terms, bias, silu -> hs in smem (stage 0) ----
    float* hs = (float*)smem;                       // [64][HS_STRIDE]
    {
        const float step = stepp[0];
        float colc[4][2], w2r[4][2], w3r[4][2];
#pragma unroll
        for (int ni = 0; ni < 4; ++ni)
#pragma unroll
            for (int j = 0; j < 2; ++j) {
                int col = wn + ni * 8 + 2 * tg + j;
                colc[ni][j] = fmaf(step, W1[(size_t)D_SZ * H_SZ + col], b1[col]);
                w2r[ni][j]  = W1[(size_t)(D_SZ + 1) * H_SZ + col];
                w3r[ni][j]  = W1[(size_t)(D_SZ + 2) * H_SZ + col];
            }
#pragma unroll
        for (int mi = 0; mi < 2; ++mi) {
            int lr0 = wm + mi * 16 + g;
            int lr1 = lr0 + 8;
            float hv0 = hn[m0 + lr0], cv0 = conf[m0 + lr0];
            float hv1 = hn[m0 + lr1], cv1 = conf[m0 + lr1];
#pragma unroll
            for (int ni = 0; ni < 4; ++ni) {
                int col0 = wn + ni * 8 + 2 * tg;
                float x00 = sum[mi][ni][0] + colc[ni][0] + hv0 * w2r[ni][0] + cv0 * w3r[ni][0];
                float x01 = sum[mi][ni][1] + colc[ni][1] + hv0 * w2r[ni][1] + cv0 * w3r[ni][1];
                float x10 = sum[mi][ni][2] + colc[ni][0] + hv1 * w2r[ni][0] + cv1 * w3r[ni][0];
                float x11 = sum[mi][ni][3] + colc[ni][1] + hv1 * w2r[ni][1] + cv1 * w3r[ni][1];
                float2 s0, s1;
                s0.x = x00 / (1.0f + expf(-x00));
                s0.y = x01 / (1.0f + expf(-x01));
                s1.x = x10 / (1.0f + expf(-x10));
                s1.y = x11 / (1.0f + expf(-x11));
                *(float2*)&hs[lr0 * HS_STRIDE + col0] = s0;
                *(float2*)&hs[lr1 * HS_STRIDE + col0] = s1;
            }
        }
    }
    __syncthreads();

    // ---- epilogue stage B: load W2 pair-permuted into stage-1 smem ----
    float2* ws2 = (float2*)&smem[STG];              // [H_SZ][32] pairs (e, e+32)
    for (int i = tid; i < H_SZ * 32; i += 256) {
        int k = i >> 5, j = i & 31;
        ws2[i] = make_float2(W2[k * E_SZ + j], W2[k * E_SZ + j + 32]);
    }
    __syncthreads();

    // ---- epilogue stage C: per-warp GEMV + top-8 + softmax for 8 rows ----
    {
        const float bz0 = b2[lane];
        const float bz1 = b2[lane + 32];
        float acc0[8], acc1[8];
#pragma unroll
        for (int rr = 0; rr < 8; ++rr) { acc0[rr] = bz0; acc1[rr] = bz1; }

        const float* hrow = &hs[(w * 8) * HS_STRIDE];
        for (int k = 0; k < H_SZ; ++k) {
            float2 wv = ws2[k * 32 + lane];
#pragma unroll
            for (int rr = 0; rr < 8; ++rr) {
                float hv = hrow[rr * HS_STRIDE + k];    // LDS broadcast
                acc0[rr] = fmaf(hv, wv.x, acc0[rr]);
                acc1[rr] = fmaf(hv, wv.y, acc1[rr]);
            }
        }

        float* out_w = out;
        float* out_l = out + (size_t)B_SZ * E_SZ;
#pragma unroll
        for (int rr = 0; rr < 8; ++rr) {
            const int r = m0 + w * 8 + rr;
            const float a0 = acc0[rr], a1 = acc1[rr];
            out_l[(size_t)r * E_SZ + lane]      = a0;
            out_l[(size_t)r * E_SZ + lane + 32] = a1;

            bool used0 = false, used1 = false;
            float tv[K_TOP];
            int   ti[K_TOP];
#pragma unroll
            for (int t = 0; t < K_TOP; ++t) {
                float mv = -3.402823466e38f;
                int   mi = 1 << 30;
                if (!used0) { mv = a0; mi = lane; }
                if (!used1 && (a1 > mv || (a1 == mv && lane + 32 < mi))) {
                    mv = a1; mi = lane + 32;
                }
#pragma unroll
                for (int off = 16; off > 0; off >>= 1) {
                    float ov = __shfl_xor_sync(0xffffffffu, mv, off);
                    int   oi = __shfl_xor_sync(0xffffffffu, mi, off);
                    if (ov > mv || (ov == mv && oi < mi)) { mv = ov; mi = oi; }
                }
                tv[t] = mv;
                ti[t] = mi;
                if (mi == lane)      used0 = true;
                if (mi == lane + 32) used1 = true;
            }

            float mx = tv[0];
            float s = 0.0f;
            float ev[K_TOP];
#pragma unroll
            for (int t = 0; t < K_TOP; ++t) { ev[t] = expf(tv[t] - mx); s += ev[t]; }
            float inv = 1.0f / s;

            float w0 = 0.0f, w1 = 0.0f;
#pragma unroll
            for (int t = 0; t < K_TOP; ++t) {
                float e = ev[t] * inv;
                if (ti[t] == lane)      w0 = e;
                if (ti[t] == lane + 32) w1 = e;
            }
            out_w[(size_t)r * E_SZ + lane]      = w0;
            out_w[(size_t)r * E_SZ + lane + 32] = w1;
        }
    }
}

// ---------------------------------------------------------------------------
extern "C" void kernel_launch(void* const* d_in, const int* in_sizes, int n_in,
                              void* d_out, int out_size) {
    const float* r_pooled    = (const float*)d_in[0];
    const float* step_frac   = (const float*)d_in[1];
    const float* hidden_norm = (const float*)d_in[2];
    const float* confidence  = (const float*)d_in[3];
    const float* W1          = (const float*)d_in[4];
    const float* b1          = (const float*)d_in[5];
    const float* W2          = (const float*)d_in[6];
    const float* b2          = (const float*)d_in[7];
    float* out = (float*)d_out;

    // Unconditional (no static guard — determinism rule); not a stream op,
    // so it is graph-capture-safe.
    cudaFuncSetAttribute(fused_router_kernel,
                         cudaFuncAttributeMaxDynamicSharedMemorySize,
                         SMEM_U32 * 4);

    fused_router_kernel<<<B_SZ / BM, 256, SMEM_U32 * 4>>>(
        r_pooled, W1, b1, step_frac, hidden_norm, confidence, W2, b2, out);
}